// round 3
// baseline (speedup 1.0000x reference)
#include <cuda_runtime.h>
#include <math.h>

// Problem constants
#define NSYS 4096      // tridiagonal system size (= NX)
#define NT   4096      // time steps
#define ROWP 4104      // padded row stride (multiple of 8 -> float4 aligned)
#define NTH  512       // threads in persistent kernel
#define ELEMS 8        // elements per thread (512*8 = 4096)
#define NWARP 16

// Scratch / parameter globals (no cudaMalloc allowed)
__device__ float g_par[8];            // 0:dt 1:inv_dt 2:tscale(=4096/tmax) 3:aconst 4:r0
__device__ float g_cp[NSYS];
__device__ float g_den[NSYS];
__device__ float g_inlet[NT + 8];
__device__ float g_U[(size_t)(NT + 1) * ROWP];   // solution history, padded rows

// ---------------------------------------------------------------------------
// Kernel 1: reduce t_max, compute scalar params, Thomas factorization (fixed
// point converges geometrically -> 192 sequential iters + constant fill),
// and the inlet table  inlet[n] = 1 + 0.5 sin(2*pi*n*dt).
// ---------------------------------------------------------------------------
__global__ void k_setup(const float* __restrict__ alpha,
                        const float* __restrict__ vel,
                        const float* __restrict__ r0p,
                        const float* __restrict__ r1p,
                        const float* __restrict__ tq, int nq) {
    __shared__ float smax[32];
    __shared__ float sbc[4];
    int tid = threadIdx.x;
    int lane = tid & 31, wid = tid >> 5;

    float m = -1e30f;
    for (int i = tid; i < nq; i += blockDim.x) m = fmaxf(m, tq[i]);
    #pragma unroll
    for (int s = 16; s > 0; s >>= 1) m = fmaxf(m, __shfl_xor_sync(0xffffffffu, m, s));
    if (lane == 0) smax[wid] = m;
    __syncthreads();

    if (tid == 0) {
        float tmax = smax[0];
        int nw = (blockDim.x + 31) >> 5;
        for (int i = 1; i < nw; i++) tmax = fmaxf(tmax, smax[i]);
        float dt = tmax / 4096.0f;
        float inv_dt = 1.0f / dt;
        float al = *alpha, ve = *vel, r0 = *r0p, r1 = *r1p;
        float r_diff = al * 10000.0f;     // alpha / dx^2, dx = 0.01
        float r_adv  = ve * 50.0f;        // vel / (2 dx)
        float aconst = r_diff + r_adv;
        float b_int  = -2.0f * r_diff - inv_dt - r1;
        float c_int  = r_diff - r_adv;
        float b_last = -aconst - inv_dt - r1;
        g_par[0] = dt; g_par[1] = inv_dt; g_par[2] = 4096.0f / tmax;
        g_par[3] = aconst; g_par[4] = r0;
        // Thomas forward elimination: contraction factor <=~0.2 -> bitwise
        // converged well before i=192; fill the rest with the fixed point.
        g_cp[0] = 0.0f; g_den[0] = 1.0f;
        float cp = 0.0f;
        for (int i = 1; i < 192; i++) {
            float den = b_int - aconst * cp;
            cp = c_int / den;
            g_den[i] = den; g_cp[i] = cp;
        }
        float denc = b_int - aconst * cp;
        sbc[0] = dt; sbc[1] = cp; sbc[2] = denc;
        g_den[NSYS - 1] = b_last - aconst * cp;   // last row: different b, c=0
        g_cp[NSYS - 1]  = 0.0f;
    }
    __syncthreads();
    float dt = sbc[0], cpc = sbc[1], denc = sbc[2];
    for (int i = 192 + tid; i < NSYS - 1; i += blockDim.x) {
        g_den[i] = denc; g_cp[i] = cpc;
    }
    const float twopi = 6.283185307179586f;
    for (int n = tid; n <= NT; n += blockDim.x)
        g_inlet[n] = 1.0f + 0.5f * sinf(twopi * ((float)n * dt));
}

// ---------------------------------------------------------------------------
// Kernel 2: persistent single-CTA time loop, ONE __syncthreads per step.
//
// dp = m + Lf*c  (c = forward carry, per thread).  The backward solve is
// linear in dp, so it splits into an m-only part (computed pre-sync,
// overlapped with the forward warp scan) and carry corrections with
// step-invariant weights:
//   u[k] = gm[k] + c*gL[k] + Lb[k]*( ex2m + Qb*Dm + sum_j W_j * c_{t+j} )
// where gL = local backscan of Lf, W_j = (prod Bfull) * gL0_{t+j}.
// Neighbor carries c_{t+j} = QfD_j*C + P_{l+j-1} use only pre-sync shuffles
// of P, so the post-sync path is one LDS + a few FMAs.
// Ping-pong smem buffers make the single barrier safe across iterations.
// ---------------------------------------------------------------------------
__global__ void __launch_bounds__(NTH, 1) k_main() {
    __shared__ float sF[2][NWARP], sD[2][NWARP];
    __shared__ float sEx[2][NWARP][8];
    __shared__ float s_inlet[NT + 8];

    int tid = threadIdx.x;
    int lane = tid & 31, wid = tid >> 5;
    int e0 = tid * ELEMS;

    float inv_dt = g_par[1], aconst = g_par[3], r0 = g_par[4];

    float av[8], cv[8], f1[8], f0[8], Lf[8], Lb[8], gL[8];
    #pragma unroll
    for (int k = 0; k < 8; k++) {
        int e = e0 + k;
        float den = g_den[e];
        float rc = 1.0f / den;
        av[k] = (e == 0) ? 0.0f : (-aconst * rc);
        cv[k] = -g_cp[e];
        f1[k] = -inv_dt * rc;
        f0[k] = r0 * (0.01f * (float)e) * rc;
    }
    Lf[0] = av[0];
    #pragma unroll
    for (int k = 1; k < 8; k++) Lf[k] = Lf[k - 1] * av[k];
    Lb[7] = cv[7];
    #pragma unroll
    for (int k = 6; k >= 0; k--) Lb[k] = cv[k] * Lb[k + 1];
    gL[7] = Lf[7];
    #pragma unroll
    for (int k = 6; k >= 0; k--) gL[k] = fmaf(cv[k], gL[k + 1], Lf[k]);
    float Bfull = Lb[0];

    // ---- forward warp-scan multipliers (step-invariant) ----
    float A = Lf[7];
    float Mf0 = (lane >= 1) ? A : 0.0f;
    float v = __shfl_up_sync(0xffffffffu, A, 1); if (lane >= 1) A *= v;
    float Mf1 = (lane >= 2) ? A : 0.0f;
    v = __shfl_up_sync(0xffffffffu, A, 2); if (lane >= 2) A *= v;
    float Mf2 = (lane >= 4) ? A : 0.0f;
    v = __shfl_up_sync(0xffffffffu, A, 4); if (lane >= 4) A *= v;
    v = __shfl_up_sync(0xffffffffu, A, 8); if (lane >= 8) A *= v;
    v = __shfl_up_sync(0xffffffffu, A, 16); if (lane >= 16) A *= v; // prefix prod
    float Qf = __shfl_up_sync(0xffffffffu, A, 1); if (lane == 0) Qf = 1.0f;
    // shifted Qf for neighbor carries c_{t+j}
    float QfD1 = __shfl_down_sync(0xffffffffu, Qf, 1);
    float QfD2 = __shfl_down_sync(0xffffffffu, Qf, 2);
    float QfD3 = __shfl_down_sync(0xffffffffu, Qf, 3);
    float QfD4 = __shfl_down_sync(0xffffffffu, Qf, 4);
    float QfD5 = __shfl_down_sync(0xffffffffu, Qf, 5);
    // Qf of the NEXT warp's lanes 0..4 (uniform interior: A^i with own A)
    float Aown = Lf[7];
    float QN1 = Aown, QN2 = QN1 * Aown, QN3 = QN2 * Aown, QN4 = QN3 * Aown;

    // ---- backward warp-scan multipliers ----
    float Bp = Bfull;
    float Mb0 = (lane <= 30) ? Bp : 0.0f;
    v = __shfl_down_sync(0xffffffffu, Bp, 1); if (lane <= 30) Bp *= v;
    float Mb1 = (lane <= 29) ? Bp : 0.0f;
    v = __shfl_down_sync(0xffffffffu, Bp, 2); if (lane <= 29) Bp *= v;
    float Mb2 = (lane <= 27) ? Bp : 0.0f;
    v = __shfl_down_sync(0xffffffffu, Bp, 4); if (lane <= 27) Bp *= v;
    v = __shfl_down_sync(0xffffffffu, Bp, 8); if (lane <= 23) Bp *= v;
    v = __shfl_down_sync(0xffffffffu, Bp, 16); if (lane <= 15) Bp *= v;
    float Qb = __shfl_down_sync(0xffffffffu, Bp, 1); if (lane == 31) Qb = 1.0f;

    // ---- carry-correction weights W_j ----
    float g01 = __shfl_down_sync(0xffffffffu, gL[0], 1);
    float g02 = __shfl_down_sync(0xffffffffu, gL[0], 2);
    float g03 = __shfl_down_sync(0xffffffffu, gL[0], 3);
    float g04 = __shfl_down_sync(0xffffffffu, gL[0], 4);
    float g05 = __shfl_down_sync(0xffffffffu, gL[0], 5);
    float B1 = __shfl_down_sync(0xffffffffu, Bfull, 1);
    float B2 = __shfl_down_sync(0xffffffffu, Bfull, 2);
    float B3 = __shfl_down_sync(0xffffffffu, Bfull, 3);
    float B4 = __shfl_down_sync(0xffffffffu, Bfull, 4);
    float W1 = g01;
    float W2 = B1 * g02;
    float W3 = B1 * B2 * g03;
    float W4 = B1 * B2 * B3 * g04;
    float W5 = B1 * B2 * B3 * B4 * g05;

    // inlet table into smem
    for (int i = tid; i <= NT; i += NTH) s_inlet[i] = g_inlet[i];

    // initial state u = 1, store row 0
    float u[8];
    #pragma unroll
    for (int k = 0; k < 8; k++) u[k] = 1.0f;
    {
        float4 one4 = make_float4(1.f, 1.f, 1.f, 1.f);
        float4* p = (float4*)(g_U + e0);
        p[0] = one4; p[1] = one4;
        if (tid == NTH - 1) g_U[NSYS] = 1.0f;
    }
    __syncthreads();

    float* row = g_U + ROWP + e0;
    float inl = s_inlet[1];
    bool notlast = (wid < NWARP - 1);
    for (int n = 0; n < NT; n++) {
        int par = n & 1;

        // ---- local forward scan of rhs (m) ----
        float m[8];
        m[0] = (tid == 0) ? inl : fmaf(u[0], f1[0], f0[0]);
        #pragma unroll
        for (int k = 1; k < 8; k++)
            m[k] = fmaf(av[k], m[k - 1], fmaf(u[k], f1[k], f0[k]));

        // ---- forward warp scan ----
        float P = m[7];
        v = __shfl_up_sync(0xffffffffu, P, 1); P = fmaf(Mf0, v, P);
        v = __shfl_up_sync(0xffffffffu, P, 2); P = fmaf(Mf1, v, P);
        v = __shfl_up_sync(0xffffffffu, P, 4); P = fmaf(Mf2, v, P);
        float ex = __shfl_up_sync(0xffffffffu, P, 1); if (lane == 0) ex = 0.0f;
        float Cown = __shfl_sync(0xffffffffu, P, 31);
        float pd1 = __shfl_down_sync(0xffffffffu, P, 1);
        float pd2 = __shfl_down_sync(0xffffffffu, P, 2);
        float pd3 = __shfl_down_sync(0xffffffffu, P, 3);
        float pd4 = __shfl_down_sync(0xffffffffu, P, 4);

        // ---- local backward scan of m (carry-free part) ----
        float gm[8];
        gm[7] = m[7];
        #pragma unroll
        for (int k = 6; k >= 0; k--) gm[k] = fmaf(cv[k], gm[k + 1], m[k]);

        // ---- backward warp scan on gm[0] ----
        float P2 = gm[0];
        v = __shfl_down_sync(0xffffffffu, P2, 1); P2 = fmaf(Mb0, v, P2);
        v = __shfl_down_sync(0xffffffffu, P2, 2); P2 = fmaf(Mb1, v, P2);
        v = __shfl_down_sync(0xffffffffu, P2, 4); P2 = fmaf(Mb2, v, P2);
        float ex2 = __shfl_down_sync(0xffffffffu, P2, 1); if (lane == 31) ex2 = 0.0f;

        if (lane == 31) sF[par][wid] = P;
        if (lane == 0)  sD[par][wid] = P2;
        if (lane < 5)   sEx[par][wid][lane] = ex;
        float inl_nx = s_inlet[n + 2];
        __syncthreads();

        // ---- post-sync: carries and solution ----
        float C  = (wid > 0) ? sF[par][wid - 1] : 0.0f;
        float Dm = notlast ? sD[par][wid + 1] : 0.0f;
        float c   = fmaf(Qf,   C, ex);
        float cn1 = fmaf(QfD1, C, P);     // c_{t+1}: ex_{l+1} == P_l
        float cn2 = fmaf(QfD2, C, pd1);
        float cn3 = fmaf(QfD3, C, pd2);
        float cn4 = fmaf(QfD4, C, pd3);
        float cn5 = fmaf(QfD5, C, pd4);
        if (lane >= 27) {  // neighbors spill into the next warp
            int nwid = notlast ? (wid + 1) : 0;
            float exn1 = sEx[par][nwid][1];
            float exn2 = sEx[par][nwid][2];
            float exn3 = sEx[par][nwid][3];
            float exn4 = sEx[par][nwid][4];
            float cN0 = Cown;                       // next warp lane0: ex=0, Qf=1
            float cN1 = fmaf(QN1, Cown, exn1);
            float cN2 = fmaf(QN2, Cown, exn2);
            float cN3 = fmaf(QN3, Cown, exn3);
            float cN4 = fmaf(QN4, Cown, exn4);
            if (!notlast) { cN0 = 0.f; cN1 = 0.f; cN2 = 0.f; cN3 = 0.f; cN4 = 0.f; }
            if (lane == 31)      { cn1 = cN0; cn2 = cN1; cn3 = cN2; cn4 = cN3; cn5 = cN4; }
            else if (lane == 30) { cn2 = cN0; cn3 = cN1; cn4 = cN2; cn5 = cN3; }
            else if (lane == 29) { cn3 = cN0; cn4 = cN1; cn5 = cN2; }
            else if (lane == 28) { cn4 = cN0; cn5 = cN1; }
            else                 { cn5 = cN0; }
        }
        float Sa = fmaf(Qb, Dm, ex2);
        float Sb = fmaf(W1, cn1, Sa);
        float Sc = fmaf(W2, cn2, W3 * cn3);
        float Sd = fmaf(W4, cn4, W5 * cn5);
        float S  = Sb + Sc + Sd;
        #pragma unroll
        for (int k = 0; k < 8; k++)
            u[k] = fmaf(Lb[k], S, fmaf(c, gL[k], gm[k]));

        // ---- store row n+1 ----
        float4* p = (float4*)row;
        p[0] = make_float4(u[0], u[1], u[2], u[3]);
        p[1] = make_float4(u[4], u[5], u[6], u[7]);
        if (tid == NTH - 1) row[NSYS - e0] = u[7];  // Neumann copy at outlet
        row += ROWP;
        inl = inl_nx;
    }
}

// ---------------------------------------------------------------------------
// Kernel 3: time interpolation  out[b] = (1-w) U[idx0] + w U[idx1]
// ---------------------------------------------------------------------------
__global__ void k_interp(const float* __restrict__ tq, float* __restrict__ out) {
    int b = blockIdx.x;
    float tn = tq[b] * g_par[2];
    float f = floorf(tn);
    int i0 = (int)f;
    i0 = max(0, min(i0, NT - 1));
    float w = tn - (float)i0;
    const float* r0 = g_U + (size_t)i0 * ROWP;
    const float* r1 = r0 + ROWP;
    float* o = out + (size_t)b * (NSYS + 1);
    for (int x = threadIdx.x; x <= NSYS; x += blockDim.x)
        o[x] = (1.0f - w) * r0[x] + w * r1[x];
}

// ---------------------------------------------------------------------------
extern "C" void kernel_launch(void* const* d_in, const int* in_sizes, int n_in,
                              void* d_out, int out_size) {
    const float* alpha = (const float*)d_in[0];
    const float* vel   = (const float*)d_in[1];
    const float* r0    = (const float*)d_in[2];
    const float* r1    = (const float*)d_in[3];
    const float* t     = (const float*)d_in[4];
    int B = in_sizes[4];

    k_setup<<<1, 1024>>>(alpha, vel, r0, r1, t, B);
    k_main<<<1, NTH>>>();
    k_interp<<<B, 256>>>(t, (float*)d_out);
}

// round 4
// speedup vs baseline: 2.2482x; 2.2482x over previous
#include <cuda_runtime.h>
#include <math.h>

// Problem constants
#define NSYS 4096      // tridiagonal system size (= NX)
#define NT   4096      // time steps
#define ROWP 4104      // padded row stride (multiple of 8 -> float4 aligned)
#define NTH  256       // threads in persistent kernel
#define ELEMS 16       // elements per thread (256*16 = 4096)
#define NWARP 8

// Scratch / parameter globals (no cudaMalloc allowed)
__device__ float g_par[8];            // 0:dt 1:inv_dt 2:tscale 3:aconst 4:r0
__device__ float g_cp[NSYS];
__device__ float g_den[NSYS];
__device__ float g_inlet[NT + 8];
__device__ unsigned char g_need[NT + 2];
__device__ float g_U[(size_t)(NT + 1) * ROWP];   // solution history, padded rows

// ---------------------------------------------------------------------------
// Kernel 1: t_max reduction, scalar params, Thomas factorization (fixed point,
// 192 iters then constant fill), inlet table, and the needed-row bitmap
// (only rows idx0[b], idx0[b]+1 are ever read by the interpolation).
// ---------------------------------------------------------------------------
__global__ void k_setup(const float* __restrict__ alpha,
                        const float* __restrict__ vel,
                        const float* __restrict__ r0p,
                        const float* __restrict__ r1p,
                        const float* __restrict__ tq, int nq) {
    __shared__ float smax[32];
    __shared__ float sbc[4];
    int tid = threadIdx.x;
    int lane = tid & 31, wid = tid >> 5;

    // zero the need bitmap while reducing t_max
    for (int i = tid; i < NT + 2; i += blockDim.x) g_need[i] = 0;

    float m = -1e30f;
    for (int i = tid; i < nq; i += blockDim.x) m = fmaxf(m, tq[i]);
    #pragma unroll
    for (int s = 16; s > 0; s >>= 1) m = fmaxf(m, __shfl_xor_sync(0xffffffffu, m, s));
    if (lane == 0) smax[wid] = m;
    __syncthreads();

    if (tid == 0) {
        float tmax = smax[0];
        int nw = (blockDim.x + 31) >> 5;
        for (int i = 1; i < nw; i++) tmax = fmaxf(tmax, smax[i]);
        float dt = tmax / 4096.0f;
        float inv_dt = 1.0f / dt;
        float al = *alpha, ve = *vel, r0 = *r0p, r1 = *r1p;
        float r_diff = al * 10000.0f;     // alpha / dx^2, dx = 0.01
        float r_adv  = ve * 50.0f;        // vel / (2 dx)
        float aconst = r_diff + r_adv;
        float b_int  = -2.0f * r_diff - inv_dt - r1;
        float c_int  = r_diff - r_adv;
        float b_last = -aconst - inv_dt - r1;
        float tscale = 4096.0f / tmax;
        g_par[0] = dt; g_par[1] = inv_dt; g_par[2] = tscale;
        g_par[3] = aconst; g_par[4] = r0;
        // Thomas forward elimination: converges geometrically, 192 is plenty
        g_cp[0] = 0.0f; g_den[0] = 1.0f;
        float cp = 0.0f;
        for (int i = 1; i < 192; i++) {
            float den = b_int - aconst * cp;
            cp = c_int / den;
            g_den[i] = den; g_cp[i] = cp;
        }
        float denc = b_int - aconst * cp;
        sbc[0] = dt; sbc[1] = cp; sbc[2] = denc; sbc[3] = tscale;
        g_den[NSYS - 1] = b_last - aconst * cp;   // last row: different b, c=0
        g_cp[NSYS - 1]  = 0.0f;
    }
    __syncthreads();
    float dt = sbc[0], cpc = sbc[1], denc = sbc[2], tscale = sbc[3];
    for (int i = 192 + tid; i < NSYS - 1; i += blockDim.x) {
        g_den[i] = denc; g_cp[i] = cpc;
    }
    const float twopi = 6.283185307179586f;
    for (int n = tid; n <= NT; n += blockDim.x)
        g_inlet[n] = 1.0f + 0.5f * sinf(twopi * ((float)n * dt));
    // mark needed rows
    for (int i = tid; i < nq; i += blockDim.x) {
        float tn = tq[i] * tscale;
        int i0 = (int)floorf(tn);
        i0 = max(0, min(i0, NT - 1));
        g_need[i0] = 1;
        g_need[i0 + 1] = 1;
    }
}

// ---------------------------------------------------------------------------
// Kernel 2: persistent single-CTA time loop, 256 threads x 16 elems.
// Two syncs per step (proven R1 structure), but:
//  - 64-elem truncation window now spans 4 lanes -> 2-round warp scans
//  - dp never materialized: gm = backscan(m) pre-barrier; carry enters via
//    P2 = c*gL[0]+gm[0] and fused apply u = Lb*S + (c*gL + gm)  (5 FMA/elem)
//  - rows not needed by the interpolation are not stored
// ---------------------------------------------------------------------------
__global__ void __launch_bounds__(NTH, 1) k_main() {
    __shared__ float sF[NWARP], sD[NWARP];
    __shared__ float s_inlet[NT + 8];
    __shared__ unsigned char s_need[NT + 2];

    int tid = threadIdx.x;
    int lane = tid & 31, wid = tid >> 5;
    int e0 = tid * ELEMS;

    float inv_dt = g_par[1], aconst = g_par[3], r0 = g_par[4];

    float av[ELEMS], cv[ELEMS], f1[ELEMS], f0[ELEMS], L[ELEMS], Lb[ELEMS];
    #pragma unroll
    for (int k = 0; k < ELEMS; k++) {
        int e = e0 + k;
        float den = g_den[e];
        float rc = 1.0f / den;
        av[k] = (e == 0) ? 0.0f : (-aconst * rc);
        cv[k] = -g_cp[e];
        f1[k] = -inv_dt * rc;
        f0[k] = r0 * (0.01f * (float)e) * rc;
    }
    // L = Lf (forward cumulative products)
    L[0] = av[0];
    #pragma unroll
    for (int k = 1; k < ELEMS; k++) L[k] = L[k - 1] * av[k];
    float A = L[ELEMS - 1];
    float Lb_[1];
    Lb[ELEMS - 1] = cv[ELEMS - 1];
    #pragma unroll
    for (int k = ELEMS - 2; k >= 0; k--) Lb[k] = cv[k] * Lb[k + 1];
    float Bfull = Lb[0];
    (void)Lb_;
    // overwrite L with gL = local backscan of Lf (in place, downward)
    #pragma unroll
    for (int k = ELEMS - 2; k >= 0; k--) L[k] = fmaf(cv[k], L[k + 1], L[k]);

    // ---- forward warp-scan multipliers (2 working rounds + Qf) ----
    float Aa = A, v;
    float Mf0 = (lane >= 1) ? Aa : 0.0f;
    v = __shfl_up_sync(0xffffffffu, Aa, 1);  if (lane >= 1)  Aa *= v;
    float Mf1 = (lane >= 2) ? Aa : 0.0f;
    v = __shfl_up_sync(0xffffffffu, Aa, 2);  if (lane >= 2)  Aa *= v;
    v = __shfl_up_sync(0xffffffffu, Aa, 4);  if (lane >= 4)  Aa *= v;
    v = __shfl_up_sync(0xffffffffu, Aa, 8);  if (lane >= 8)  Aa *= v;
    v = __shfl_up_sync(0xffffffffu, Aa, 16); if (lane >= 16) Aa *= v;
    float Qf = __shfl_up_sync(0xffffffffu, Aa, 1); if (lane == 0) Qf = 1.0f;

    // ---- backward warp-scan multipliers ----
    float Bb = Bfull;
    float Mb0 = (lane <= 30) ? Bb : 0.0f;
    v = __shfl_down_sync(0xffffffffu, Bb, 1);  if (lane <= 30) Bb *= v;
    float Mb1 = (lane <= 29) ? Bb : 0.0f;
    v = __shfl_down_sync(0xffffffffu, Bb, 2);  if (lane <= 29) Bb *= v;
    v = __shfl_down_sync(0xffffffffu, Bb, 4);  if (lane <= 27) Bb *= v;
    v = __shfl_down_sync(0xffffffffu, Bb, 8);  if (lane <= 23) Bb *= v;
    v = __shfl_down_sync(0xffffffffu, Bb, 16); if (lane <= 15) Bb *= v;
    float Qb = __shfl_down_sync(0xffffffffu, Bb, 1); if (lane == 31) Qb = 1.0f;

    // inlet + need tables into smem
    for (int i = tid; i <= NT; i += NTH) s_inlet[i] = g_inlet[i];
    for (int i = tid; i < NT + 2; i += NTH) s_need[i] = g_need[i];

    // initial state u = 1, store row 0 (always needed as idx0 can be 0)
    float u[ELEMS];
    #pragma unroll
    for (int k = 0; k < ELEMS; k++) u[k] = 1.0f;
    {
        float4 one4 = make_float4(1.f, 1.f, 1.f, 1.f);
        float4* p = (float4*)(g_U + e0);
        p[0] = one4; p[1] = one4; p[2] = one4; p[3] = one4;
        if (tid == NTH - 1) g_U[NSYS] = 1.0f;
    }
    __syncthreads();

    float* row = g_U + ROWP + e0;
    float inl = s_inlet[1];
    for (int n = 0; n < NT; n++) {
        // ---- local forward scan of rhs: m ----
        float m[ELEMS];
        m[0] = (tid == 0) ? inl : fmaf(u[0], f1[0], f0[0]);
        #pragma unroll
        for (int k = 1; k < ELEMS; k++)
            m[k] = fmaf(av[k], m[k - 1], fmaf(u[k], f1[k], f0[k]));

        // ---- forward warp scan (2 rounds, 64-elem window) ----
        float P = m[ELEMS - 1];
        v = __shfl_up_sync(0xffffffffu, P, 1); P = fmaf(Mf0, v, P);
        v = __shfl_up_sync(0xffffffffu, P, 2); P = fmaf(Mf1, v, P);
        float ex = __shfl_up_sync(0xffffffffu, P, 1); if (lane == 0) ex = 0.0f;
        if (lane == 31) sF[wid] = P;

        // ---- local backscan of m in place (overlaps barrier arrival) ----
        #pragma unroll
        for (int k = ELEMS - 2; k >= 0; k--) m[k] = fmaf(cv[k], m[k + 1], m[k]);

        float inl_nx = s_inlet[n + 2];
        bool need = s_need[n + 1] != 0;
        __syncthreads();

        // ---- forward carry, then backward warp scan ----
        float C = (wid > 0) ? sF[wid - 1] : 0.0f;
        float c = fmaf(Qf, C, ex);
        float P2 = fmaf(c, L[0], m[0]);
        v = __shfl_down_sync(0xffffffffu, P2, 1); P2 = fmaf(Mb0, v, P2);
        v = __shfl_down_sync(0xffffffffu, P2, 2); P2 = fmaf(Mb1, v, P2);
        float ex2 = __shfl_down_sync(0xffffffffu, P2, 1); if (lane == 31) ex2 = 0.0f;
        if (lane == 0) sD[wid] = P2;
        __syncthreads();

        float D = (wid < NWARP - 1) ? sD[wid + 1] : 0.0f;
        float S = fmaf(Qb, D, ex2);
        #pragma unroll
        for (int k = 0; k < ELEMS; k++)
            u[k] = fmaf(Lb[k], S, fmaf(c, L[k], m[k]));

        // ---- store row n+1 only if the interpolation will read it ----
        if (need) {
            float4* p = (float4*)row;
            p[0] = make_float4(u[0],  u[1],  u[2],  u[3]);
            p[1] = make_float4(u[4],  u[5],  u[6],  u[7]);
            p[2] = make_float4(u[8],  u[9],  u[10], u[11]);
            p[3] = make_float4(u[12], u[13], u[14], u[15]);
            if (tid == NTH - 1) row[NSYS - e0] = u[15];  // Neumann outlet copy
        }
        row += ROWP;
        inl = inl_nx;
    }
}

// ---------------------------------------------------------------------------
// Kernel 3: time interpolation  out[b] = (1-w) U[idx0] + w U[idx1]
// ---------------------------------------------------------------------------
__global__ void k_interp(const float* __restrict__ tq, float* __restrict__ out) {
    int b = blockIdx.x;
    float tn = tq[b] * g_par[2];
    float f = floorf(tn);
    int i0 = (int)f;
    i0 = max(0, min(i0, NT - 1));
    float w = tn - (float)i0;
    const float* r0 = g_U + (size_t)i0 * ROWP;
    const float* r1 = r0 + ROWP;
    float* o = out + (size_t)b * (NSYS + 1);
    for (int x = threadIdx.x; x <= NSYS; x += blockDim.x)
        o[x] = (1.0f - w) * r0[x] + w * r1[x];
}

// ---------------------------------------------------------------------------
extern "C" void kernel_launch(void* const* d_in, const int* in_sizes, int n_in,
                              void* d_out, int out_size) {
    const float* alpha = (const float*)d_in[0];
    const float* vel   = (const float*)d_in[1];
    const float* r0    = (const float*)d_in[2];
    const float* r1    = (const float*)d_in[3];
    const float* t     = (const float*)d_in[4];
    int B = in_sizes[4];

    k_setup<<<1, 1024>>>(alpha, vel, r0, r1, t, B);
    k_main<<<1, NTH>>>();
    k_interp<<<B, 256>>>(t, (float*)d_out);
}

// round 5
// speedup vs baseline: 2.4060x; 1.0702x over previous
#include <cuda_runtime.h>
#include <math.h>

// Problem constants
#define NSYS 4096      // tridiagonal system size (= NX)
#define NT   4096      // time steps
#define ROWP 4104      // padded row stride (multiple of 8 -> float4 aligned)
#define NTH  256       // threads in persistent kernel
#define ELEMS 16       // elements per thread (256*16 = 4096)
#define NWARP 8
#define NDEN 256       // first NDEN Thomas rows stored exactly; rest converged

// Globals (no cudaMalloc allowed)
__device__ float g_par[8];            // [2] = tscale for k_interp
__device__ float g_U[(size_t)(NT + 1) * ROWP];   // solution history, padded rows

// ---------------------------------------------------------------------------
// Persistent single-CTA kernel: setup prologue + NT-step time loop.
// ONE __syncthreads per step:
//  - 1-round warp scans (|A| = |prod av over 16 elems| <= ~8e-7, so window
//    of 2 lanes = 32 elems truncates at A^2 ~ 1e-12)
//  - backward warp scan runs on gm[0] PRE-barrier; the carry cross-term is
//    restored post-barrier by a single weight W1 = gL0_{t+1} (higher terms
//    decay by Bfull ~ 8e-7 each -> negligible)
//  - post-barrier path: 2 LDS + 4 FMA + independent apply
//  - rows not read by the interpolation are not stored
// ---------------------------------------------------------------------------
__global__ void __launch_bounds__(NTH, 1) k_main(
        const float* __restrict__ alpha, const float* __restrict__ vel,
        const float* __restrict__ r0p,   const float* __restrict__ r1p,
        const float* __restrict__ tq, int nq) {
    __shared__ float sF[2][NWARP], sD[2][NWARP];
    __shared__ float s_inlet[NT + 8];
    __shared__ unsigned char s_need[NT + 2];
    __shared__ float s_den[NDEN], s_cp[NDEN];
    __shared__ float sPar[8];   // 0:dt 1:inv_dt 2:tscale 3:aconst 4:r0 5:denc 6:cpc 7:den_last
    __shared__ float smax[NWARP];

    int tid = threadIdx.x;
    int lane = tid & 31, wid = tid >> 5;
    int e0 = tid * ELEMS;

    // ================= setup prologue =================
    for (int i = tid; i < NT + 2; i += NTH) s_need[i] = 0;

    float mx = -1e30f;
    for (int i = tid; i < nq; i += NTH) mx = fmaxf(mx, tq[i]);
    #pragma unroll
    for (int s = 16; s > 0; s >>= 1) mx = fmaxf(mx, __shfl_xor_sync(0xffffffffu, mx, s));
    if (lane == 0) smax[wid] = mx;
    __syncthreads();

    if (tid == 0) {
        float tmax = smax[0];
        for (int i = 1; i < NWARP; i++) tmax = fmaxf(tmax, smax[i]);
        float dt = tmax / 4096.0f;
        float inv_dt = 1.0f / dt;
        float al = *alpha, ve = *vel, r0 = *r0p, r1 = *r1p;
        float r_diff = al * 10000.0f;     // alpha / dx^2, dx = 0.01
        float r_adv  = ve * 50.0f;        // vel / (2 dx)
        float aconst = r_diff + r_adv;
        float b_int  = -2.0f * r_diff - inv_dt - r1;
        float c_int  = r_diff - r_adv;
        float b_last = -aconst - inv_dt - r1;
        float tscale = 4096.0f / tmax;
        sPar[0] = dt; sPar[1] = inv_dt; sPar[2] = tscale;
        sPar[3] = aconst; sPar[4] = r0;
        g_par[2] = tscale;
        // Thomas forward elimination: contraction ~<=0.25/iter -> bitwise
        // converged well before NDEN/2; store exact prefix, rest = fixpoint.
        s_cp[0] = 0.0f; s_den[0] = 1.0f;
        float cp = 0.0f;
        for (int i = 1; i < NDEN; i++) {
            float den = b_int - aconst * cp;
            cp = c_int / den;
            s_den[i] = den; s_cp[i] = cp;
        }
        sPar[5] = b_int - aconst * cp;   // converged den
        sPar[6] = cp;                    // converged cp
        sPar[7] = b_last - aconst * cp;  // last-row den
    }
    __syncthreads();

    float dt = sPar[0], inv_dt = sPar[1], tscale = sPar[2];
    float aconst = sPar[3], r0 = sPar[4];
    float denc = sPar[5], cpc = sPar[6], den_last = sPar[7];

    const float twopi = 6.283185307179586f;
    for (int n = tid; n <= NT; n += NTH)
        s_inlet[n] = 1.0f + 0.5f * sinf(twopi * ((float)n * dt));
    for (int i = tid; i < nq; i += NTH) {
        float tn = tq[i] * tscale;
        int i0 = (int)floorf(tn);
        i0 = max(0, min(i0, NT - 1));
        s_need[i0] = 1;
        s_need[i0 + 1] = 1;
    }

    // ================= per-thread coefficients =================
    float av[ELEMS], cv[ELEMS], f1[ELEMS], f0[ELEMS], L[ELEMS], Lb[ELEMS];
    #pragma unroll
    for (int k = 0; k < ELEMS; k++) {
        int e = e0 + k;
        float den = (e < NDEN) ? s_den[e] : denc;
        float cp  = (e < NDEN) ? s_cp[e]  : cpc;
        if (e == NSYS - 1) { den = den_last; cp = 0.0f; }
        float rc = 1.0f / den;
        av[k] = (e == 0) ? 0.0f : (-aconst * rc);
        cv[k] = -cp;
        f1[k] = -inv_dt * rc;
        f0[k] = r0 * (0.01f * (float)e) * rc;
    }
    // L = Lf (forward cumulative products of av)
    L[0] = av[0];
    #pragma unroll
    for (int k = 1; k < ELEMS; k++) L[k] = L[k - 1] * av[k];
    float A = L[ELEMS - 1];
    Lb[ELEMS - 1] = cv[ELEMS - 1];
    #pragma unroll
    for (int k = ELEMS - 2; k >= 0; k--) Lb[k] = cv[k] * Lb[k + 1];
    float Bfull = Lb[0];
    // overwrite L with gL = local backscan of Lf (gL[15] = Lf[15] stays)
    #pragma unroll
    for (int k = ELEMS - 2; k >= 0; k--) L[k] = fmaf(cv[k], L[k + 1], L[k]);

    // ---- warp-scan constants ----
    float v;
    float Mf0 = (lane >= 1) ? A : 0.0f;          // 1-round forward scan
    // exact prefix product for Qf (one-time)
    float Aa = A;
    v = __shfl_up_sync(0xffffffffu, Aa, 1);  if (lane >= 1)  Aa *= v;
    v = __shfl_up_sync(0xffffffffu, Aa, 2);  if (lane >= 2)  Aa *= v;
    v = __shfl_up_sync(0xffffffffu, Aa, 4);  if (lane >= 4)  Aa *= v;
    v = __shfl_up_sync(0xffffffffu, Aa, 8);  if (lane >= 8)  Aa *= v;
    v = __shfl_up_sync(0xffffffffu, Aa, 16); if (lane >= 16) Aa *= v;
    float Qf = __shfl_up_sync(0xffffffffu, Aa, 1); if (lane == 0) Qf = 1.0f;
    float QfD1 = __shfl_down_sync(0xffffffffu, Qf, 1);
    if (lane == 31) QfD1 = 0.0f;                 // lane31: cn1 = own P

    float Mb0 = (lane <= 30) ? Bfull : 0.0f;     // 1-round backward scan
    float Bb = Bfull;
    v = __shfl_down_sync(0xffffffffu, Bb, 1);  if (lane <= 30) Bb *= v;
    v = __shfl_down_sync(0xffffffffu, Bb, 2);  if (lane <= 29) Bb *= v;
    v = __shfl_down_sync(0xffffffffu, Bb, 4);  if (lane <= 27) Bb *= v;
    v = __shfl_down_sync(0xffffffffu, Bb, 8);  if (lane <= 23) Bb *= v;
    v = __shfl_down_sync(0xffffffffu, Bb, 16); if (lane <= 15) Bb *= v;
    float Qb = __shfl_down_sync(0xffffffffu, Bb, 1); if (lane == 31) Qb = 1.0f;

    // carry cross-term weight: W1 = gL0 of thread t+1
    float W1 = __shfl_down_sync(0xffffffffu, L[0], 1);  // lane31 self = interior OK
    if (tid == NTH - 1) W1 = 0.0f;               // no neighbor past the domain

    // ================= initial state: u = 1, row 0 =================
    float m[ELEMS];
    #pragma unroll
    for (int k = 0; k < ELEMS; k++) m[k] = 1.0f;
    {
        float4 one4 = make_float4(1.f, 1.f, 1.f, 1.f);
        float4* p = (float4*)(g_U + e0);
        p[0] = one4; p[1] = one4; p[2] = one4; p[3] = one4;
        if (tid == NTH - 1) g_U[NSYS] = 1.0f;
    }
    __syncthreads();

    // ================= time loop =================
    float* row = g_U + ROWP + e0;
    float inl = s_inlet[1];
    for (int n = 0; n < NT; n++) {
        int par = n & 1;

        // ---- rhs + local forward scan (in place: m holds u on entry) ----
        float b0 = fmaf(m[0], f1[0], f0[0]);
        m[0] = (tid == 0) ? inl : b0;
        #pragma unroll
        for (int k = 1; k < ELEMS; k++)
            m[k] = fmaf(av[k], m[k - 1], fmaf(m[k], f1[k], f0[k]));

        // ---- forward warp scan (1 round) ----
        float P = m[ELEMS - 1];
        v = __shfl_up_sync(0xffffffffu, P, 1); P = fmaf(Mf0, v, P);
        float ex = __shfl_up_sync(0xffffffffu, P, 1); if (lane == 0) ex = 0.0f;
        if (lane == 31) sF[par][wid] = P;

        // ---- local backscan of m in place ----
        #pragma unroll
        for (int k = ELEMS - 2; k >= 0; k--) m[k] = fmaf(cv[k], m[k + 1], m[k]);

        // ---- backward warp scan on gm[0] (1 round), PRE-barrier ----
        float P2 = m[0];
        v = __shfl_down_sync(0xffffffffu, P2, 1); P2 = fmaf(Mb0, v, P2);
        float ex2 = __shfl_down_sync(0xffffffffu, P2, 1); if (lane == 31) ex2 = 0.0f;
        if (lane == 0) sD[par][wid] = P2;

        float inl_nx = s_inlet[n + 2];
        bool need = s_need[n + 1] != 0;
        __syncthreads();

        // ---- post-barrier: carries + fused apply ----
        float C  = (wid > 0) ? sF[par][wid - 1] : 0.0f;
        float Dm = (wid < NWARP - 1) ? sD[par][wid + 1] : 0.0f;
        float c   = fmaf(Qf,   C, ex);
        float cn1 = fmaf(QfD1, C, P);           // carry of thread t+1
        float Sa  = fmaf(Qb, Dm, ex2);
        float S   = fmaf(W1, cn1, Sa);
        #pragma unroll
        for (int k = 0; k < ELEMS; k++)
            m[k] = fmaf(Lb[k], S, fmaf(c, L[k], m[k]));   // m = u (next step)

        // ---- store row n+1 only if the interpolation will read it ----
        if (need) {
            float4* p = (float4*)row;
            p[0] = make_float4(m[0],  m[1],  m[2],  m[3]);
            p[1] = make_float4(m[4],  m[5],  m[6],  m[7]);
            p[2] = make_float4(m[8],  m[9],  m[10], m[11]);
            p[3] = make_float4(m[12], m[13], m[14], m[15]);
            if (tid == NTH - 1) row[NSYS - e0] = m[15];  // Neumann outlet copy
        }
        row += ROWP;
        inl = inl_nx;
    }
}

// ---------------------------------------------------------------------------
// Interpolation:  out[b] = (1-w) U[idx0] + w U[idx1]
// ---------------------------------------------------------------------------
__global__ void k_interp(const float* __restrict__ tq, float* __restrict__ out) {
    int b = blockIdx.x;
    float tn = tq[b] * g_par[2];
    float f = floorf(tn);
    int i0 = (int)f;
    i0 = max(0, min(i0, NT - 1));
    float w = tn - (float)i0;
    const float* r0 = g_U + (size_t)i0 * ROWP;
    const float* r1 = r0 + ROWP;
    float* o = out + (size_t)b * (NSYS + 1);
    for (int x = threadIdx.x; x <= NSYS; x += blockDim.x)
        o[x] = (1.0f - w) * r0[x] + w * r1[x];
}

// ---------------------------------------------------------------------------
extern "C" void kernel_launch(void* const* d_in, const int* in_sizes, int n_in,
                              void* d_out, int out_size) {
    const float* alpha = (const float*)d_in[0];
    const float* vel   = (const float*)d_in[1];
    const float* r0    = (const float*)d_in[2];
    const float* r1    = (const float*)d_in[3];
    const float* t     = (const float*)d_in[4];
    int B = in_sizes[4];

    k_main<<<1, NTH>>>(alpha, vel, r0, r1, t, B);
    k_interp<<<B, 256>>>(t, (float*)d_out);
}